// round 1
// baseline (speedup 1.0000x reference)
#include <cuda_runtime.h>
#include <math.h>

#define BSZ   2
#define TSEQ  2048
#define DMODEL 1024
#define NHEAD 16
#define DHEAD 64
#define MROWS (BSZ * TSEQ)   // 4096

// Scratch (allocation-free rule: __device__ globals)
__device__ float g_q[MROWS * DMODEL];
__device__ float g_k[MROWS * DMODEL];
__device__ float g_v[MROWS * DMODEL];
__device__ float g_attn[MROWS * DMODEL];

// ---------------------------------------------------------------------------
// GEMM: C[M,N] = A[M,K] @ W[N,K]^T + bias[N]
// M = 4096, N = K = 1024 (fixed). 128x128x16 tiles, 256 threads, 8x8 micro.
// ---------------------------------------------------------------------------
__global__ __launch_bounds__(256) void gemm_bias_kernel(
    const float* __restrict__ A, const float* __restrict__ W,
    const float* __restrict__ bias, float* __restrict__ C)
{
    const int BM = 128, BN = 128, BK = 16;
    __shared__ float As[BK][BM + 4];
    __shared__ float Ws[BK][BN + 4];

    const int tid = threadIdx.x;
    const int bm = blockIdx.y * BM;
    const int bn = blockIdx.x * BN;
    const int tm = (tid >> 4) << 3;   // 0..120
    const int tn = (tid & 15) << 3;   // 0..120

    float acc[8][8];
#pragma unroll
    for (int i = 0; i < 8; i++)
#pragma unroll
        for (int j = 0; j < 8; j++) acc[i][j] = 0.0f;

    for (int k0 = 0; k0 < DMODEL; k0 += BK) {
        // Cooperative loads: 128x16 per operand, 2 float4 per thread each.
#pragma unroll
        for (int i = 0; i < 2; i++) {
            int v   = (tid << 1) + i;       // 0..511
            int row = v >> 2;               // 0..127
            int c4  = (v & 3) << 2;         // 0,4,8,12
            float4 a = *(const float4*)(A + (size_t)(bm + row) * DMODEL + k0 + c4);
            As[c4 + 0][row] = a.x; As[c4 + 1][row] = a.y;
            As[c4 + 2][row] = a.z; As[c4 + 3][row] = a.w;
            float4 w = *(const float4*)(W + (size_t)(bn + row) * DMODEL + k0 + c4);
            Ws[c4 + 0][row] = w.x; Ws[c4 + 1][row] = w.y;
            Ws[c4 + 2][row] = w.z; Ws[c4 + 3][row] = w.w;
        }
        __syncthreads();

#pragma unroll
        for (int k = 0; k < BK; k++) {
            float ra[8], rb[8];
#pragma unroll
            for (int i = 0; i < 8; i++) ra[i] = As[k][tm + i];
#pragma unroll
            for (int i = 0; i < 8; i++) rb[i] = Ws[k][tn + i];
#pragma unroll
            for (int i = 0; i < 8; i++)
#pragma unroll
                for (int j = 0; j < 8; j++) acc[i][j] += ra[i] * rb[j];
        }
        __syncthreads();
    }

    // Epilogue: add bias, vectorized stores.
#pragma unroll
    for (int i = 0; i < 8; i++) {
#pragma unroll
        for (int j4 = 0; j4 < 8; j4 += 4) {
            float4 r;
            r.x = acc[i][j4 + 0] + bias[bn + tn + j4 + 0];
            r.y = acc[i][j4 + 1] + bias[bn + tn + j4 + 1];
            r.z = acc[i][j4 + 2] + bias[bn + tn + j4 + 2];
            r.w = acc[i][j4 + 3] + bias[bn + tn + j4 + 3];
            *(float4*)(C + (size_t)(bm + tm + i) * DMODEL + bn + tn + j4) = r;
        }
    }
}

// ---------------------------------------------------------------------------
// Causal flash attention. Grid: (T/64, H, B), 64 threads/block.
// Each thread owns one query row entirely (private online softmax).
// K/V tiles in smem (broadcast float4 reads), scores staged in Ss[j][tid].
// ---------------------------------------------------------------------------
__global__ __launch_bounds__(64) void attn_kernel(
    const float* __restrict__ Q, const float* __restrict__ K,
    const float* __restrict__ V, float* __restrict__ O)
{
    __shared__ float4 Ks4[64][16];   // 16 KB
    __shared__ float4 Vs4[64][16];   // 16 KB
    __shared__ float  Ss[64][64];    // 16 KB ([j][tid], lane-contiguous)

    const int qt  = blockIdx.x;          // query tile
    const int h   = blockIdx.y;
    const int b   = blockIdx.z;
    const int tid = threadIdx.x;         // query row within tile
    const int qrow = qt * 64 + tid;

    const size_t row_base = (size_t)(b * TSEQ + qrow) * DMODEL + h * DHEAD;

    // Load this thread's query row into registers.
    float q[64];
#pragma unroll
    for (int d4 = 0; d4 < 16; d4++) {
        float4 t = *(const float4*)(Q + row_base + d4 * 4);
        q[d4 * 4 + 0] = t.x; q[d4 * 4 + 1] = t.y;
        q[d4 * 4 + 2] = t.z; q[d4 * 4 + 3] = t.w;
    }

    float o[64];
#pragma unroll
    for (int d = 0; d < 64; d++) o[d] = 0.0f;
    float m = -1e30f, l = 0.0f;

    for (int kt = 0; kt <= qt; kt++) {
        __syncthreads();  // previous tile's smem fully consumed
        // Cooperative coalesced load of K and V tiles (64x64 floats each).
        const float* Kbase = K + (size_t)(b * TSEQ + kt * 64) * DMODEL + h * DHEAD;
        const float* Vbase = V + (size_t)(b * TSEQ + kt * 64) * DMODEL + h * DHEAD;
#pragma unroll
        for (int i = 0; i < 16; i++) {
            int v   = i * 64 + tid;   // 0..1023
            int row = v >> 4;         // 0..63
            int c4  = v & 15;         // 0..15
            Ks4[row][c4] = *(const float4*)(Kbase + (size_t)row * DMODEL + c4 * 4);
            Vs4[row][c4] = *(const float4*)(Vbase + (size_t)row * DMODEL + c4 * 4);
        }
        __syncthreads();

        const bool diag = (kt == qt);

        // Pass 1: scores for all 64 keys, tile max.
        float tmax = -1e30f;
#pragma unroll 2
        for (int j = 0; j < 64; j++) {
            float a0 = 0.f, a1 = 0.f, a2 = 0.f, a3 = 0.f;
#pragma unroll
            for (int d4 = 0; d4 < 16; d4++) {
                float4 kv = Ks4[j][d4];
                a0 += q[d4 * 4 + 0] * kv.x;
                a1 += q[d4 * 4 + 1] * kv.y;
                a2 += q[d4 * 4 + 2] * kv.z;
                a3 += q[d4 * 4 + 3] * kv.w;
            }
            float s = (a0 + a1) + (a2 + a3);
            s *= 0.125f;                          // 1/sqrt(64)
            if (diag && j > tid) s = -1e30f;      // causal mask
            Ss[j][tid] = s;
            tmax = fmaxf(tmax, s);
        }

        // Online softmax update.
        float mnew  = fmaxf(m, tmax);
        float alpha = __expf(m - mnew);
        l *= alpha;
#pragma unroll
        for (int d = 0; d < 64; d++) o[d] *= alpha;

        // Pass 2: P*V accumulation.
#pragma unroll 2
        for (int j = 0; j < 64; j++) {
            float p = __expf(Ss[j][tid] - mnew);
            l += p;
#pragma unroll
            for (int d4 = 0; d4 < 16; d4++) {
                float4 vv = Vs4[j][d4];
                o[d4 * 4 + 0] += p * vv.x;
                o[d4 * 4 + 1] += p * vv.y;
                o[d4 * 4 + 2] += p * vv.z;
                o[d4 * 4 + 3] += p * vv.w;
            }
        }
        m = mnew;
    }

    // Normalize and write out.
    float inv = 1.0f / l;
#pragma unroll
    for (int d4 = 0; d4 < 16; d4++) {
        float4 r;
        r.x = o[d4 * 4 + 0] * inv;
        r.y = o[d4 * 4 + 1] * inv;
        r.z = o[d4 * 4 + 2] * inv;
        r.w = o[d4 * 4 + 3] * inv;
        *(float4*)(O + row_base + d4 * 4) = r;
    }
}

// ---------------------------------------------------------------------------
extern "C" void kernel_launch(void* const* d_in, const int* in_sizes, int n_in,
                              void* d_out, int out_size)
{
    (void)in_sizes; (void)n_in; (void)out_size;
    const float* query = (const float*)d_in[0];
    const float* key_  = (const float*)d_in[1];
    const float* value = (const float*)d_in[2];
    const float* q_w   = (const float*)d_in[3];
    const float* q_b   = (const float*)d_in[4];
    const float* k_w   = (const float*)d_in[5];
    const float* k_b   = (const float*)d_in[6];
    const float* v_w   = (const float*)d_in[7];
    const float* v_b   = (const float*)d_in[8];
    const float* o_w   = (const float*)d_in[9];
    const float* o_b   = (const float*)d_in[10];
    float* out = (float*)d_out;

    float *qp, *kp, *vp, *ap;
    cudaGetSymbolAddress((void**)&qp, g_q);
    cudaGetSymbolAddress((void**)&kp, g_k);
    cudaGetSymbolAddress((void**)&vp, g_v);
    cudaGetSymbolAddress((void**)&ap, g_attn);

    dim3 ggrid(DMODEL / 128, MROWS / 128);   // (8, 32)
    gemm_bias_kernel<<<ggrid, 256>>>(query, q_w, q_b, qp);
    gemm_bias_kernel<<<ggrid, 256>>>(key_,  k_w, k_b, kp);
    gemm_bias_kernel<<<ggrid, 256>>>(value, v_w, v_b, vp);

    attn_kernel<<<dim3(TSEQ / 64, NHEAD, BSZ), 64>>>(qp, kp, vp, ap);

    gemm_bias_kernel<<<ggrid, 256>>>(ap, o_w, o_b, out);
}